// round 8
// baseline (speedup 1.0000x reference)
#include <cuda_runtime.h>
#include <cuda_bf16.h>

// PosMLP, two kernels:
//  A) gen_weights: weights[q][65] = queries[q] @ w_gen^T + b_gen -> __device__ scratch.
//     2 warps/query; each warp-iteration computes 4 outputs with a 6-shfl
//     multi-value butterfly reduction (results land on lanes 0/8/16/24).
//  B) raster: thread = (q, w, h-half); 24 rows each, processed 2 rows/iter for ILP;
//     packed fma.rn.f32x2 inner loop.
//
// Shapes fixed by setup_inputs: B=2, Q=900 (NQ=1800), C=256, HIDDEN=16, H=W=48.

#define CC   256
#define NW   65
#define HD   16
#define HH   48
#define WW   48
#define NQ   1800

__device__ float g_wt[NQ * NW];   // 468 KB scratch (L2-resident)

// ---------------------------------------------------------------------------
// Kernel A: 450 blocks x 256 threads (8 warps). Warp gw -> (q = gw/2, hs = gw&1).
// Iter it computes n = nb..nb+3 with nb = hs*4 + it*8 (covers 0..64, interleaved).
// Lane owns channels [lane*8, lane*8+8) via two float4 loads.
// ---------------------------------------------------------------------------
__global__ __launch_bounds__(256) void gen_weights_kernel(
    const float* __restrict__ queries,   // [1800][256]
    const float* __restrict__ w_gen,     // [65][256]
    const float* __restrict__ b_gen)     // [65]
{
    const int warp = threadIdx.x >> 5;
    const int lane = threadIdx.x & 31;
    const int gw   = blockIdx.x * 8 + warp;   // 0..3599
    const int q    = gw >> 1;
    const int hs   = gw & 1;

    const float4* qrow = (const float4*)(queries + (size_t)q * CC);
    const float4  q0 = qrow[lane * 2];
    const float4  q1 = qrow[lane * 2 + 1];

    const bool lo16 = (lane & 16) == 0;
    const bool lo8  = (lane & 8) == 0;

    for (int it = 0; it < 9; it++) {
        const int nb = hs * 4 + it * 8;       // 4-row group base
        if (nb >= NW) break;                  // hs=1, it=8

        float s[4];
        #pragma unroll
        for (int r = 0; r < 4; r++) {
            const int n = min(nb + r, NW - 1);            // clamp (only nb=64 case)
            const float4* wr = (const float4*)(w_gen + (size_t)n * CC);
            const float4 w0 = wr[lane * 2];
            const float4 w1 = wr[lane * 2 + 1];
            float t0 = 0.f, t1 = 0.f;
            t0 = fmaf(q0.x, w0.x, t0);  t1 = fmaf(q0.y, w0.y, t1);
            t0 = fmaf(q0.z, w0.z, t0);  t1 = fmaf(q0.w, w0.w, t1);
            t0 = fmaf(q1.x, w1.x, t0);  t1 = fmaf(q1.y, w1.y, t1);
            t0 = fmaf(q1.z, w1.z, t0);  t1 = fmaf(q1.w, w1.w, t1);
            s[r] = t0 + t1;
        }

        // 6-shfl reduction of 4 values.
        // Stage xor16: value0/1 collapse onto lanes 0-15, value2/3 onto 16-31.
        float a0 = lo16 ? s[0] : s[2];
        float b0 = lo16 ? s[2] : s[0];
        a0 += __shfl_xor_sync(0xffffffffu, b0, 16);
        float a1 = lo16 ? s[1] : s[3];
        float b1 = lo16 ? s[3] : s[1];
        a1 += __shfl_xor_sync(0xffffffffu, b1, 16);
        // Stage xor8: one value per 8-lane group.
        float c = lo8 ? a0 : a1;
        float d = lo8 ? a1 : a0;
        c += __shfl_xor_sync(0xffffffffu, d, 8);
        // Final reduce within 8-lane groups.
        c += __shfl_xor_sync(0xffffffffu, c, 4);
        c += __shfl_xor_sync(0xffffffffu, c, 2);
        c += __shfl_xor_sync(0xffffffffu, c, 1);

        if ((lane & 7) == 0) {
            const int n = nb + (lane >> 3);
            if (n < NW)
                g_wt[q * NW + n] = c + b_gen[n];
        }
    }
}

// ---------------------------------------------------------------------------
// Packed fp32x2 FMA (sm_103a FFMA2 — only reachable via PTX fma.rn.f32x2).
// ---------------------------------------------------------------------------
union F2U { float2 f; unsigned long long u; };

__device__ __forceinline__ float2 ffma2(float2 a, float2 b, float2 c) {
    F2U A, B, C, D;
    A.f = a; B.f = b; C.f = c;
    asm("fma.rn.f32x2 %0, %1, %2, %3;"
        : "=l"(D.u) : "l"(A.u), "l"(B.u), "l"(C.u));
    return D.f;
}

// ---------------------------------------------------------------------------
// Kernel B: rasterizer, h-split in halves, 2 rows per loop iteration.
// 1350 blocks x 128 threads. gtid -> q = gtid/96; hh = (gtid%96)/48; w = gtid%48.
// 8 independent accumulator chains per thread.
// ---------------------------------------------------------------------------
__global__ __launch_bounds__(128, 8) void raster_kernel(
    const float* __restrict__ pos,       // [1800][4] (cx, cy, bw, bh)
    float* __restrict__ out)             // [1800][48][48]
{
    const int gtid = blockIdx.x * 128 + threadIdx.x;
    const int q    = gtid / 96;
    const int rem  = gtid - q * 96;
    const int hh   = rem / 48;           // 0 or 1
    const int w    = rem - hh * 48;

    const float* __restrict__ wt = g_wt + q * NW;

    const float4 p  = ((const float4*)pos)[q];  // cx, cy, bw, bh
    const float cx = p.x, cy = p.y, bw = p.z, bh = p.w;

    const float rx     = ((w + 0.5f) * (1.0f / WW) - cx) / bw;
    const float inv_bh = 1.0f / bh;

    // Pack per-pair (k = 2j, 2j+1) params. Fold rx*w1x + b1 into tw.
    float2 w1y2[HD / 2], tw2[HD / 2], w22[HD / 2];
    const float2 rx2 = make_float2(rx, rx);
    #pragma unroll
    for (int j = 0; j < HD / 2; j++) {
        w1y2[j]     = make_float2(wt[4 * j],     wt[4 * j + 2]);      // w1y_{2j}, w1y_{2j+1}
        float2 w1x2 = make_float2(wt[4 * j + 1], wt[4 * j + 3]);      // w1x_{2j}, w1x_{2j+1}
        float2 b12  = make_float2(wt[2 * HD + 2 * j], wt[2 * HD + 2 * j + 1]);
        tw2[j]      = ffma2(rx2, w1x2, b12);
        w22[j]      = make_float2(wt[3 * HD + 2 * j], wt[3 * HD + 2 * j + 1]);
    }
    const float b2 = wt[4 * HD];

    const int   h0    = hh * (HH / 2);
    const float y0    = ((h0 + 0.5f) * (1.0f / HH) - cy) * inv_bh;
    const float ystep = (1.0f / HH) * inv_bh;

    float* obase = out + (size_t)q * (HH * WW) + h0 * WW + w;

    #pragma unroll 3
    for (int h2 = 0; h2 < HH / 4; h2++) {            // 12 iters, 2 rows each
        const float  ryA  = fmaf((float)(2 * h2), ystep, y0);
        const float  ryB  = ryA + ystep;
        const float2 ryA2 = make_float2(ryA, ryA);
        const float2 ryB2 = make_float2(ryB, ryB);
        float2 aA0 = make_float2(b2, 0.f), aA1 = make_float2(0.f, 0.f);
        float2 aB0 = make_float2(b2, 0.f), aB1 = make_float2(0.f, 0.f);
        #pragma unroll
        for (int j = 0; j < HD / 2; j += 2) {
            float2 vA0 = ffma2(ryA2, w1y2[j],     tw2[j]);
            float2 vA1 = ffma2(ryA2, w1y2[j + 1], tw2[j + 1]);
            float2 vB0 = ffma2(ryB2, w1y2[j],     tw2[j]);
            float2 vB1 = ffma2(ryB2, w1y2[j + 1], tw2[j + 1]);
            vA0.x = fmaxf(vA0.x, 0.f);  vA0.y = fmaxf(vA0.y, 0.f);
            vA1.x = fmaxf(vA1.x, 0.f);  vA1.y = fmaxf(vA1.y, 0.f);
            vB0.x = fmaxf(vB0.x, 0.f);  vB0.y = fmaxf(vB0.y, 0.f);
            vB1.x = fmaxf(vB1.x, 0.f);  vB1.y = fmaxf(vB1.y, 0.f);
            aA0 = ffma2(vA0, w22[j],     aA0);
            aA1 = ffma2(vA1, w22[j + 1], aA1);
            aB0 = ffma2(vB0, w22[j],     aB0);
            aB1 = ffma2(vB1, w22[j + 1], aB1);
        }
        obase[(2 * h2)     * WW] = (aA0.x + aA0.y) + (aA1.x + aA1.y);
        obase[(2 * h2 + 1) * WW] = (aB0.x + aB0.y) + (aB1.x + aB1.y);
    }
}

extern "C" void kernel_launch(void* const* d_in, const int* in_sizes, int n_in,
                              void* d_out, int out_size) {
    const float* queries = (const float*)d_in[0];
    const float* pos     = (const float*)d_in[1];
    const float* w_gen   = (const float*)d_in[2];
    const float* b_gen   = (const float*)d_in[3];
    float* out = (float*)d_out;

    gen_weights_kernel<<<450, 256>>>(queries, w_gen, b_gen);
    raster_kernel<<<(NQ * WW * 2) / 128, 128>>>(pos, out);
}